// round 13
// baseline (speedup 1.0000x reference)
#include <cuda_runtime.h>
#include <cuda_fp16.h>
#include <math.h>

// Problem constants
#define BATCH 8
#define NPOS 1024            // 32x32
#define DIM 128
#define HEADS 8
#define GRID 32              // H = W = 32
#define POSITIONS (BATCH*NPOS)   // 8192

#define GEMM_SMEM 71680      // gemmU: 2x(128x72) + 2x(64x136) halfs; aliases 128x132 f32 U tile
#define GEMMY_SMEM 79872     // gemmY: 3x(64x72) + 3x(64x136) halfs
#define CR_SMEM 49152        // colcum_regions: 1024 pos x (8 dims + 4 pad) floats

// ---------------- scratch (static device memory; no allocs allowed) -------
__device__ float g_S[POSITIONS*DIM];             // row-cumsum image
__device__ float g_P1[DIM*DIM];                  // Wq @ Wk^T
__device__ float g_P2[DIM*DIM];                  // Wv @ Wo
__device__ float g_bu[HEADS*DIM];                // 0.25 * bqkv_h @ P1
__device__ float g_bfinal[DIM];

__device__ __half g_XNh[POSITIONS*DIM];          // layernormed x, fp16
__device__ __half g_Rh[POSITIONS*4*DIM];         // region means fp16 [pos][r][d]
__device__ __half g_Mh[DIM*HEADS*DIM];           // 0.25 * Wqkv_h @ P1, [128][1024]
__device__ __half g_W3h[HEADS*DIM*DIM];          // P2 @ Wout_h, [1024][128]
__device__ __half g_Ch[POSITIONS*HEADS*DIM];     // aggregated context, [8192][1024]

// ---------------- helpers ---------------------------------------------------
__device__ __forceinline__ unsigned smem_u32(const void* p) {
    return (unsigned)__cvta_generic_to_shared(p);
}
__device__ __forceinline__ void ldmatrix_x4(unsigned* r, unsigned addr) {
    asm volatile("ldmatrix.sync.aligned.m8n8.x4.shared.b16 {%0,%1,%2,%3}, [%4];"
        : "=r"(r[0]), "=r"(r[1]), "=r"(r[2]), "=r"(r[3]) : "r"(addr));
}
__device__ __forceinline__ void ldmatrix_x2t(unsigned* r, unsigned addr) {
    asm volatile("ldmatrix.sync.aligned.m8n8.x2.trans.shared.b16 {%0,%1}, [%2];"
        : "=r"(r[0]), "=r"(r[1]) : "r"(addr));
}
__device__ __forceinline__ void mma_f16(float* d, const unsigned* a, const unsigned* b) {
    asm volatile("mma.sync.aligned.m16n8k16.row.col.f32.f16.f16.f32 "
        "{%0,%1,%2,%3}, {%4,%5,%6,%7}, {%8,%9}, {%0,%1,%2,%3};"
        : "+f"(d[0]), "+f"(d[1]), "+f"(d[2]), "+f"(d[3])
        : "r"(a[0]), "r"(a[1]), "r"(a[2]), "r"(a[3]), "r"(b[0]), "r"(b[1]));
}
__device__ __forceinline__ void cp_async16(void* smem_dst, const void* gsrc) {
    asm volatile("cp.async.ca.shared.global [%0], [%1], 16;"
        :: "r"(smem_u32(smem_dst)), "l"(gsrc));
}

// ---------------- 64x64-tile fp32 matmul for weight precompute --------------
template<int MODE>
__device__ void mm64(const float* __restrict__ A, int lda,
                     const float* __restrict__ B, int ldb, int transB,
                     float* __restrict__ C, __half* __restrict__ Ch,
                     int ldc, int row0, int col0, float scale)
{
    __shared__ float As[16][64];
    __shared__ float Bs[16][68];
    const int tid = threadIdx.x;
    const int ty = tid >> 4, tx = tid & 15;
    float acc[4][4];
#pragma unroll
    for (int i = 0; i < 4; i++)
#pragma unroll
        for (int j = 0; j < 4; j++) acc[i][j] = 0.f;

    for (int k0 = 0; k0 < 128; k0 += 16) {
        for (int t = tid; t < 1024; t += 256) {
            int m = t >> 4, kk = t & 15;
            As[kk][m] = A[(row0+m)*lda + k0 + kk];
        }
        for (int t = tid; t < 1024; t += 256) {
            int kk = t >> 6, n = t & 63;
            Bs[kk][n] = transB ? B[(col0+n)*ldb + k0 + kk] : B[(k0+kk)*ldb + col0 + n];
        }
        __syncthreads();
#pragma unroll
        for (int kk = 0; kk < 16; kk++) {
            float a[4], b[4];
#pragma unroll
            for (int i = 0; i < 4; i++) a[i] = As[kk][ty*4+i];
#pragma unroll
            for (int j = 0; j < 4; j++) b[j] = Bs[kk][tx*4+j];
#pragma unroll
            for (int i = 0; i < 4; i++)
#pragma unroll
                for (int j = 0; j < 4; j++) acc[i][j] += a[i]*b[j];
        }
        __syncthreads();
    }
#pragma unroll
    for (int i = 0; i < 4; i++)
#pragma unroll
        for (int j = 0; j < 4; j++) {
            int r = row0 + ty*4 + i, c = col0 + tx*4 + j;
            if (MODE == 0) C[r*ldc + c] = acc[i][j];
            else           Ch[r*ldc + c] = __float2half(acc[i][j] * scale);
        }
}

// ---------------- precompute stage A: P1 = Wq@Wk^T, P2 = Wv@Wo, bfinal ------
__global__ void precompA3(const float* __restrict__ Wq, const float* __restrict__ Wk,
                          const float* __restrict__ Wv, const float* __restrict__ Wo,
                          const float* __restrict__ Wout, const float* __restrict__ bo,
                          const float* __restrict__ bout)
{
    int blk = blockIdx.x;
    if (blk < 4) {
        mm64<0>(Wq, DIM, Wk, DIM, 1, g_P1, 0, DIM, (blk>>1)*64, (blk&1)*64, 1.f);
    } else if (blk < 8) {
        int q = blk - 4;
        mm64<0>(Wv, DIM, Wo, DIM, 0, g_P2, 0, DIM, (q>>1)*64, (q&1)*64, 1.f);
    } else {
        __shared__ float part[256];
        int e = threadIdx.x & 127, half = threadIdx.x >> 7;
        float s = 0.f;
#pragma unroll 8
        for (int c = half*512; c < half*512 + 512; c++) s += bo[c & 127] * Wout[c*128 + e];
        part[threadIdx.x] = s;
        __syncthreads();
        if (half == 0) g_bfinal[e] = part[e] + part[128+e] + bout[e];
    }
}

// ---------------- precompute stage B: M_h, W3_h, bu -------------------------
__global__ void precompB3(const float* __restrict__ Wqkv, const float* __restrict__ bqkv,
                          const float* __restrict__ Wout)
{
    int blk = blockIdx.x;
    if (blk < 32) {
        int h = blk >> 2, q = blk & 3;
        mm64<1>(Wqkv + h*128, 3*HEADS*DIM, g_P1, DIM, 0, 0,
                g_Mh + h*DIM, HEADS*DIM, (q>>1)*64, (q&1)*64, 0.25f);
    } else if (blk < 64) {
        int h = (blk-32) >> 2, q = (blk-32) & 3;
        mm64<1>(g_P2, DIM, Wout + h*DIM*DIM, DIM, 0, 0,
                g_W3h + h*DIM*DIM, DIM, (q>>1)*64, (q&1)*64, 1.f);
    } else {
        for (int o = threadIdx.x; o < HEADS*DIM; o += 256) {
            int h = o >> 7, d2 = o & 127;
            float s = 0.f;
#pragma unroll 8
            for (int c = 0; c < 128; c++) s += bqkv[h*128+c] * g_P1[c*128+d2];
            g_bu[o] = 0.25f * s;
        }
    }
}

// ---------------- fused layernorm + row cumsum ------------------------------
__global__ __launch_bounds__(256) void ln_rowcum(const float* __restrict__ x,
                                                 const float* __restrict__ g,
                                                 const float* __restrict__ b)
{
    __shared__ float xs[32][128];
    const int bh = blockIdx.x;
    const int tid = threadIdx.x;
    const int wid = tid >> 5, lane = tid & 31;

    float4 g4 = ((const float4*)g)[lane];
    float4 b4 = ((const float4*)b)[lane];

#pragma unroll
    for (int i = 0; i < 4; i++) {
        int p = wid*4 + i;
        int row = bh*GRID + p;
        float4 v = ((const float4*)x)[row*32 + lane];
        float s  = v.x + v.y + v.z + v.w;
        float s2 = v.x*v.x + v.y*v.y + v.z*v.z + v.w*v.w;
#pragma unroll
        for (int o = 16; o > 0; o >>= 1) {
            s  += __shfl_xor_sync(0xffffffffu, s, o);
            s2 += __shfl_xor_sync(0xffffffffu, s2, o);
        }
        float mu = s * (1.f/128.f);
        float var = s2 * (1.f/128.f) - mu*mu;
        float inv = rsqrtf(var + 1e-5f);
        float4 xn;
        xn.x = (v.x - mu)*inv*g4.x + b4.x;
        xn.y = (v.y - mu)*inv*g4.y + b4.y;
        xn.z = (v.z - mu)*inv*g4.z + b4.z;
        xn.w = (v.w - mu)*inv*g4.w + b4.w;
        *(float4*)&xs[p][lane*4] = xn;
        *(__half2*)&g_XNh[row*DIM + lane*4]     = __floats2half2_rn(xn.x, xn.y);
        *(__half2*)&g_XNh[row*DIM + lane*4 + 2] = __floats2half2_rn(xn.z, xn.w);
    }
    __syncthreads();
    if (tid < 128) {
        float run = 0.f;
#pragma unroll
        for (int w = 0; w < GRID; w++) {
            run += xs[w][tid];
            g_S[(bh*GRID + w)*DIM + tid] = run;
        }
    }
}

// ---------------- fused column cumsum + region means (512 threads) ----------
// Block = (batch, 8-dim chunk). Split column scan (two h-halves + carry),
// thread-per-position means phase (2 positions/thread).
__global__ __launch_bounds__(512) void colcum_regions()
{
    extern __shared__ float S[];                 // [pos][12], dims at [0..7]
    __shared__ float carry[256];
    const int b  = blockIdx.x >> 4;
    const int d0 = (blockIdx.x & 15) * 8;
    const int tid = threadIdx.x;

    // ---- load slab: 2 positions per thread --------------------------------
#pragma unroll
    for (int i = 0; i < 2; i++) {
        int pos = i*512 + tid;
        const float4* src = (const float4*)&g_S[((size_t)b*NPOS + pos)*DIM + d0];
        float4 v0 = src[0], v1 = src[1];
        *(float4*)&S[pos*12]     = v0;
        *(float4*)&S[pos*12 + 4] = v1;
    }
    __syncthreads();

    // ---- column scan: split into two h-halves with carry ------------------
    {
        int item = tid & 255;                    // (w, dd)
        int half = tid >> 8;                     // 0 or 1
        int w = item >> 3, dd = item & 7;
        int h0 = half * 16;
        float v[16];
#pragma unroll
        for (int i = 0; i < 16; i++) v[i] = S[((h0+i)*GRID + w)*12 + dd];
        float run = 0.f;
#pragma unroll
        for (int i = 0; i < 16; i++) { run += v[i]; v[i] = run; }
        if (half == 0) carry[item] = v[15];
        __syncthreads();
        float c = (half == 1) ? carry[item] : 0.f;
#pragma unroll
        for (int i = 0; i < 16; i++) S[((h0+i)*GRID + w)*12 + dd] = v[i] + c;
    }
    __syncthreads();

    // ---- means phase: thread per position, 2 positions/thread -------------
#define LOAD8(dst, idx) do { \
        *(float4*)&dst[0] = *(float4*)&S[(idx)*12]; \
        *(float4*)&dst[4] = *(float4*)&S[(idx)*12 + 4]; } while (0)

#pragma unroll 1
    for (int it = 0; it < 2; it++) {
        int pos = it*512 + tid;
        int h = pos >> 5, w = pos & 31;

        float vhw[8], vhW[8], vHw[8], vHW[8];
        float vh1w[8], vh1W[8], vhw1[8], vHw1[8], vh1w1[8];
#pragma unroll
        for (int j = 0; j < 8; j++)
            vh1w[j] = vh1W[j] = vhw1[j] = vHw1[j] = vh1w1[j] = 0.f;

        LOAD8(vhw, h*GRID + w);
        LOAD8(vhW, h*GRID + 31);
        LOAD8(vHw, 31*GRID + w);
        LOAD8(vHW, 31*GRID + 31);
        if (h > 0) {
            LOAD8(vh1w, (h-1)*GRID + w);
            LOAD8(vh1W, (h-1)*GRID + 31);
            if (w > 0) LOAD8(vh1w1, (h-1)*GRID + w-1);
        }
        if (w > 0) {
            LOAD8(vhw1, h*GRID + w-1);
            LOAD8(vHw1, 31*GRID + w-1);
        }

        float hp1 = (float)(h+1), wp1 = (float)(w+1);
        float hr = (float)(GRID - h), wr = (float)(GRID - w);
        float i1 = __fdividef(1.f, hp1*wp1);
        float i2 = __fdividef(1.f, hp1*wr);
        float i3 = __fdividef(1.f, hr*wp1);
        float i4 = __fdividef(1.f, hr*wr);

        uint4 o0, o1, o2, o3;
        __half2* p0 = (__half2*)&o0;
        __half2* p1 = (__half2*)&o1;
        __half2* p2 = (__half2*)&o2;
        __half2* p3 = (__half2*)&o3;
#pragma unroll
        for (int j = 0; j < 4; j++) {
            int e0 = j*2, e1 = j*2 + 1;
            p0[j] = __floats2half2_rn(vhw[e0]*i1, vhw[e1]*i1);
            p1[j] = __floats2half2_rn((vhW[e0] - vhw1[e0])*i2,
                                      (vhW[e1] - vhw1[e1])*i2);
            p2[j] = __floats2half2_rn((vHw[e0] - vh1w[e0])*i3,
                                      (vHw[e1] - vh1w[e1])*i3);
            p3[j] = __floats2half2_rn(
                (vHW[e0] - vh1W[e0] - vHw1[e0] + vh1w1[e0])*i4,
                (vHW[e1] - vh1W[e1] - vHw1[e1] + vh1w1[e1])*i4);
        }
        __half* R = g_Rh + (size_t)(b*NPOS + pos)*4*DIM + d0;
        *(uint4*)&R[0]     = o0;
        *(uint4*)&R[DIM]   = o1;
        *(uint4*)&R[2*DIM] = o2;
        *(uint4*)&R[3*DIM] = o3;
    }
#undef LOAD8
}

// ---------------- fused: U-GEMM (fp16, K=128) + softmax + aggregate ---------
__global__ __launch_bounds__(256) void gemmU_fused()
{
    extern __shared__ char sbuf[];
    __half* As = (__half*)sbuf;                  // 2 x 128x72
    __half* Bs = (__half*)(sbuf + 36864);        // 2 x 64x136
    float* Uf = (float*)sbuf;                    // 128x132 (aliases A/B)

    const int tid = threadIdx.x;
    const int wid = tid >> 5, lane = tid & 31;
    const int wm = wid & 1, wn = wid >> 1;       // warp tile 64x32
    const int m0 = blockIdx.x * 128;
    const int h  = blockIdx.y;
    const int n0 = h * 128;

    float acc[4][4][4];
#pragma unroll
    for (int mt = 0; mt < 4; mt++)
#pragma unroll
        for (int nt = 0; nt < 4; nt++)
#pragma unroll
            for (int q = 0; q < 4; q++) acc[mt][nt][q] = 0.f;

    auto LOAD = [&](int s, int buf) {
        int k0 = s * 64;
#pragma unroll
        for (int i = 0; i < 4; i++) {
            int c = tid + i*256;
            int row = c >> 3, col8 = (c & 7) * 8;
            cp_async16(As + buf*9216 + row*72 + col8,
                       g_XNh + (m0+row)*DIM + k0 + col8);
        }
#pragma unroll
        for (int i = 0; i < 4; i++) {
            int c = tid + i*256;
            int kr = c >> 4, col8 = (c & 15) * 8;
            cp_async16(Bs + buf*8704 + kr*136 + col8,
                       g_Mh + (k0+kr)*(HEADS*DIM) + n0 + col8);
        }
        asm volatile("cp.async.commit_group;");
    };

    const unsigned as_base = smem_u32(As), bs_base = smem_u32(Bs);
    unsigned a_off[4], b_off[4];
#pragma unroll
    for (int mt = 0; mt < 4; mt++)
        a_off[mt] = ((wm*64 + mt*16 + (lane & 15))*72 + (lane >> 4)*8)*2;
#pragma unroll
    for (int nt = 0; nt < 4; nt++)
        b_off[nt] = ((lane & 15)*136 + wn*32 + nt*8)*2;

    auto COMPUTE = [&](int buf) {
#pragma unroll
        for (int kk = 0; kk < 4; kk++) {
            unsigned af[4][4];
#pragma unroll
            for (int mt = 0; mt < 4; mt++)
                ldmatrix_x4(af[mt], as_base + buf*18432 + a_off[mt] + kk*32);
#pragma unroll
            for (int nt = 0; nt < 4; nt++) {
                unsigned bfr[2];
                ldmatrix_x2t(bfr, bs_base + buf*17408 + b_off[nt] + kk*4352);
#pragma unroll
                for (int mt = 0; mt < 4; mt++) mma_f16(acc[mt][nt], af[mt], bfr);
            }
        }
    };

    LOAD(0, 0);
    LOAD(1, 1);
    asm volatile("cp.async.wait_group 1;");
    __syncthreads();
    COMPUTE(0);
    __syncthreads();
    asm volatile("cp.async.wait_group 0;");
    __syncthreads();
    COMPUTE(1);
    __syncthreads();

    // ---- write U tile (acc + scaled bias) into smem fp32 ------------------
    const int tr = lane >> 2, tc = (lane & 3)*2;
    const int r0 = wm*64, c0 = wn*32;
#pragma unroll
    for (int mt = 0; mt < 4; mt++)
#pragma unroll
        for (int nt = 0; nt < 4; nt++) {
            int row = r0 + mt*16 + tr, col = c0 + nt*8 + tc;
            float b0 = g_bu[n0 + col], b1 = g_bu[n0 + col + 1];
            *(float2*)&Uf[row*132 + col] =
                make_float2(acc[mt][nt][0] + b0, acc[mt][nt][1] + b1);
            *(float2*)&Uf[(row+8)*132 + col] =
                make_float2(acc[mt][nt][2] + b0, acc[mt][nt][3] + b1);
        }
    __syncthreads();

    // ---- epilogue: 2 positions per iteration (independent shuffle chains) -
    for (int i = 0; i < 8; i++) {
        int p[2]   = { wid*16 + i, wid*16 + i + 8 };
        int gpos[2] = { m0 + p[0], m0 + p[1] };
        float2 f[2][2][4];
        float s[2][4];
#pragma unroll
        for (int q = 0; q < 2; q++) {
            const __half* Rp = g_Rh + (size_t)gpos[q]*4*DIM;
            s[q][0] = s[q][1] = s[q][2] = s[q][3] = 0.f;
#pragma unroll
            for (int c2 = 0; c2 < 2; c2++) {
                int d = lane*2 + c2*64;
                float2 u = *(float2*)&Uf[p[q]*132 + d];
                f[q][c2][0] = __half22float2(*(const __half2*)&Rp[d]);
                f[q][c2][1] = __half22float2(*(const __half2*)&Rp[DIM + d]);
                f[q][c2][2] = __half22float2(*(const __half2*)&Rp[2*DIM + d]);
                f[q][c2][3] = __half22float2(*(const __half2*)&Rp[3*DIM + d]);
#pragma unroll
                for (int r = 0; r < 4; r++)
                    s[q][r] += u.x*f[q][c2][r].x + u.y*f[q][c2][r].y;
            }
        }
#pragma unroll
        for (int o = 16; o > 0; o >>= 1)
#pragma unroll
            for (int q = 0; q < 2; q++)
#pragma unroll
                for (int r = 0; r < 4; r++)
                    s[q][r] += __shfl_xor_sync(0xffffffffu, s[q][r], o);

#pragma unroll
        for (int q = 0; q < 2; q++) {
            float m = fmaxf(fmaxf(s[q][0], s[q][1]), fmaxf(s[q][2], s[q][3]));
            float e0 = expf(s[q][0] - m), e1 = expf(s[q][1] - m);
            float e2 = expf(s[q][2] - m), e3 = expf(s[q][3] - m);
            float inv = 1.f / (e0 + e1 + e2 + e3);
            float p0 = e0*inv, p1 = e1*inv, p2 = e2*inv, p3 = e3*inv;
#pragma unroll
            for (int c2 = 0; c2 < 2; c2++) {
                int d = lane*2 + c2*64;
                float cx = p0*f[q][c2][0].x + p1*f[q][c2][1].x
                         + p2*f[q][c2][2].x + p3*f[q][c2][3].x;
                float cy = p0*f[q][c2][0].y + p1*f[q][c2][1].y
                         + p2*f[q][c2][2].y + p3*f[q][c2][3].y;
                *(__half2*)&g_Ch[(size_t)gpos[q]*(HEADS*DIM) + n0 + d] =
                    __floats2half2_rn(cx, cy);
            }
        }
    }
}

// ---------------- Y = C @ W3cat + bfinal -> out (3-stage pipeline) ----------
__global__ __launch_bounds__(256) void gemmY3(float* __restrict__ out)
{
    extern __shared__ char sbuf[];
    __half* As = (__half*)sbuf;                  // 3 x 64x72
    __half* Bs = (__half*)(sbuf + 27648);        // 3 x 64x136

    const int tid = threadIdx.x;
    const int wid = tid >> 5, lane = tid & 31;
    const int wm = wid & 1, wn = wid >> 1;       // warp tile 32x32
    const int m0 = blockIdx.x * 64;

    float acc[2][4][4];
#pragma unroll
    for (int mt = 0; mt < 2; mt++)
#pragma unroll
        for (int nt = 0; nt < 4; nt++)
#pragma unroll
            for (int q = 0; q < 4; q++) acc[mt][nt][q] = 0.f;

    auto LOAD = [&](int s, int buf) {
        int k0 = s * 64;
#pragma unroll
        for (int i = 0; i < 2; i++) {
            int c = tid + i*256;
            int row = c >> 3, col8 = (c & 7) * 8;
            cp_async16(As + buf*4608 + row*72 + col8,
                       g_Ch + (size_t)(m0+row)*(HEADS*DIM) + k0 + col8);
        }
#pragma unroll
        for (int i = 0; i < 4; i++) {
            int c = tid + i*256;
            int kr = c >> 4, col8 = (c & 15) * 8;
            cp_async16(Bs + buf*8704 + kr*136 + col8,
                       g_W3h + (k0+kr)*DIM + col8);
        }
        asm volatile("cp.async.commit_group;");
    };

    const unsigned as_base = smem_u32(As), bs_base = smem_u32(Bs);
    unsigned a_off[2], b_off[4];
#pragma unroll
    for (int mt = 0; mt < 2; mt++)
        a_off[mt] = ((wm*32 + mt*16 + (lane & 15))*72 + (lane >> 4)*8)*2;
#pragma unroll
    for (int nt = 0; nt < 4; nt++)
        b_off[nt] = ((lane & 15)*136 + wn*32 + nt*8)*2;

    auto COMPUTE = [&](int buf) {
#pragma unroll
        for (int kk = 0; kk < 4; kk++) {
            unsigned af[2][4];
#pragma unroll
            for (int mt = 0; mt < 2; mt++)
                ldmatrix_x4(af[mt], as_base + buf*9216 + a_off[mt] + kk*32);
#pragma unroll
            for (int nt = 0; nt < 4; nt++) {
                unsigned bfr[2];
                ldmatrix_x2t(bfr, bs_base + buf*17408 + b_off[nt] + kk*4352);
#pragma unroll
                for (int mt = 0; mt < 2; mt++) mma_f16(acc[mt][nt], af[mt], bfr);
            }
        }
    };

    LOAD(0, 0);
    LOAD(1, 1);
    for (int s = 0; s < 16; s++) {
        if (s < 15) asm volatile("cp.async.wait_group 1;");
        else        asm volatile("cp.async.wait_group 0;");
        __syncthreads();
        if (s < 14) LOAD(s+2, (s+2)%3);
        COMPUTE(s%3);
    }

    const int tr = lane >> 2, tc = (lane & 3)*2;
#pragma unroll
    for (int mt = 0; mt < 2; mt++)
#pragma unroll
        for (int nt = 0; nt < 4; nt++) {
            int row = m0 + wm*32 + mt*16 + tr, col = wn*32 + nt*8 + tc;
            float b0 = g_bfinal[col], b1 = g_bfinal[col+1];
            *(float2*)&out[(size_t)row*DIM + col] =
                make_float2(acc[mt][nt][0] + b0, acc[mt][nt][1] + b1);
            *(float2*)&out[(size_t)(row+8)*DIM + col] =
                make_float2(acc[mt][nt][2] + b0, acc[mt][nt][3] + b1);
        }
}

// ---------------- launch -----------------------------------------------------
extern "C" void kernel_launch(void* const* d_in, const int* in_sizes, int n_in,
                              void* d_out, int out_size)
{
    const float* x    = (const float*)d_in[0];
    const float* ln_g = (const float*)d_in[1];
    const float* ln_b = (const float*)d_in[2];
    const float* Wqkv = (const float*)d_in[3];
    const float* bqkv = (const float*)d_in[4];
    const float* Wq   = (const float*)d_in[5];
    const float* Wk   = (const float*)d_in[6];
    const float* Wv   = (const float*)d_in[7];
    const float* Wo   = (const float*)d_in[8];
    const float* bo   = (const float*)d_in[9];
    const float* Wout = (const float*)d_in[10];
    const float* bout = (const float*)d_in[11];
    float* out = (float*)d_out;

    // One-time setup (first call is the non-captured correctness run).
    static cudaStream_t s_side = nullptr;
    static cudaEvent_t s_fork = nullptr, s_join = nullptr;
    if (s_side == nullptr) {
        cudaStreamCreateWithFlags(&s_side, cudaStreamNonBlocking);
        cudaEventCreateWithFlags(&s_fork, cudaEventDisableTiming);
        cudaEventCreateWithFlags(&s_join, cudaEventDisableTiming);
        cudaFuncSetAttribute(gemmU_fused, cudaFuncAttributeMaxDynamicSharedMemorySize, GEMM_SMEM);
        cudaFuncSetAttribute(gemmY3,      cudaFuncAttributeMaxDynamicSharedMemorySize, GEMMY_SMEM);
        cudaFuncSetAttribute(colcum_regions, cudaFuncAttributeMaxDynamicSharedMemorySize, CR_SMEM);
    }

    // Fork: weight precompute on side stream, data chain on main stream.
    cudaEventRecord(s_fork, 0);
    cudaStreamWaitEvent(s_side, s_fork, 0);

    precompA3<<<9, 256, 0, s_side>>>(Wq, Wk, Wv, Wo, Wout, bo, bout);
    precompB3<<<65, 256, 0, s_side>>>(Wqkv, bqkv, Wout);
    cudaEventRecord(s_join, s_side);

    ln_rowcum<<<BATCH*GRID, 256>>>(x, ln_g, ln_b);
    colcum_regions<<<BATCH*16, 512, CR_SMEM>>>();

    // Join: gemmU needs M/bu (side) + XN/regions (main).
    cudaStreamWaitEvent(0, s_join, 0);

    gemmU_fused<<<dim3(POSITIONS/128, HEADS), 256, GEMM_SMEM>>>();
    gemmY3<<<POSITIONS/64, 256, GEMMY_SMEM>>>(out);
}